// round 15
// baseline (speedup 1.0000x reference)
#include <cuda_runtime.h>
#include <cuda_fp16.h>
#include <math.h>
#include <stdint.h>

#define TLEN  2048
#define BSZ   4
#define EDIM  768
#define NH    12
#define HD    64
#define E3    (3*EDIM)
#define L2E   1.4426950408889634f

// ---------------- scratch (no allocation allowed) ----------------
__device__ __half g_qin [TLEN*BSZ*EDIM];        // query fp16
__device__ __half g_winh[E3*EDIM];              // in_proj_weight fp16
__device__ __half g_wouth[EDIM*EDIM];           // out_proj_weight fp16
__device__ __half g_maskh[TLEN*TLEN];           // attn_mask * log2(e), fp16
__device__ __half g_qh[BSZ*NH*TLEN*HD];         // [bh][t][d], RoPE'd, pre-scaled log2e/8
__device__ __half g_kh[BSZ*NH*TLEN*HD];         // [bh][t][d], RoPE'd
__device__ __half g_vh[BSZ*NH*TLEN*HD];         // [bh][t][d]
__device__ __half g_attnh[TLEN*BSZ*EDIM];       // [T*B, E] fp16
__device__ int    g_mask_nz;                    // static 0; set if mask nonzero (idempotent)

// 10000^(-j/32) = 10^(-j/8), exact double literals
__device__ const double ROPE_INVF[32] = {
    1.0,
    0.74989420933245582, 0.56234132519034907, 0.42169650342858224,
    0.31622776601683794, 0.23713737056616552, 0.17782794100389228,
    0.13335214321633241,
    0.1,
    0.074989420933245582, 0.056234132519034907, 0.042169650342858224,
    0.031622776601683794, 0.023713737056616552, 0.017782794100389228,
    0.013335214321633241,
    0.01,
    0.0074989420933245582, 0.0056234132519034907, 0.0042169650342858224,
    0.0031622776601683794, 0.0023713737056616552, 0.0017782794100389228,
    0.0013335214321633241,
    0.001,
    0.00074989420933245582, 0.00056234132519034907, 0.00042169650342858224,
    0.00031622776601683794, 0.00023713737056616552, 0.00017782794100389228,
    0.00013335214321633241
};

// ======================= helpers =======================
__device__ __forceinline__ uint32_t smem_u32(const void* p) {
    uint32_t a;
    asm("{ .reg .u64 t; cvta.to.shared.u64 t, %1; cvt.u32.u64 %0, t; }" : "=r"(a) : "l"(p));
    return a;
}
__device__ __forceinline__ void cp16(uint32_t dst, const void* src) {
    asm volatile("cp.async.cg.shared.global [%0], [%1], 16;" :: "r"(dst), "l"(src));
}
#define CP_COMMIT() asm volatile("cp.async.commit_group;" ::: "memory")
#define CP_WAIT0()  asm volatile("cp.async.wait_group 0;" ::: "memory")

#define LDSM_X4(r0, r1, r2, r3, addr) \
    asm volatile("ldmatrix.sync.aligned.m8n8.x4.shared.b16 {%0,%1,%2,%3}, [%4];" \
        : "=r"(r0), "=r"(r1), "=r"(r2), "=r"(r3) : "r"(addr))
#define LDSM_X4T(r0, r1, r2, r3, addr) \
    asm volatile("ldmatrix.sync.aligned.m8n8.x4.trans.shared.b16 {%0,%1,%2,%3}, [%4];" \
        : "=r"(r0), "=r"(r1), "=r"(r2), "=r"(r3) : "r"(addr))

__device__ __forceinline__ void mma_f16(float c[4], const uint32_t a[4],
                                        uint32_t b0, uint32_t b1) {
    asm volatile(
        "mma.sync.aligned.m16n8k16.row.col.f32.f16.f16.f32 "
        "{%0,%1,%2,%3}, {%4,%5,%6,%7}, {%8,%9}, {%0,%1,%2,%3};\n"
        : "+f"(c[0]), "+f"(c[1]), "+f"(c[2]), "+f"(c[3])
        : "r"(a[0]), "r"(a[1]), "r"(a[2]), "r"(a[3]), "r"(b0), "r"(b1));
}
__device__ __forceinline__ uint32_t cvt_h2(float lo, float hi) {
    uint32_t r;
    asm("cvt.rn.f16x2.f32 %0, %2, %1;" : "=r"(r) : "f"(lo), "f"(hi));
    return r;
}
__device__ __forceinline__ uint32_t hadd2u(uint32_t a, uint32_t b) {
    uint32_t r;
    asm("add.rn.f16x2 %0, %1, %2;" : "=r"(r) : "r"(a), "r"(b));
    return r;
}
__device__ __forceinline__ uint32_t ex2_h2(uint32_t x) {
    uint32_t r;
    asm("ex2.approx.f16x2 %0, %1;" : "=r"(r) : "r"(x));
    return r;
}

// ---------------- fp32 -> fp16 convert (query, win, wout, mask*log2e) ----------------
#define CVT_N1 ((TLEN*BSZ*EDIM)/4)
#define CVT_N2 ((E3*EDIM)/4)
#define CVT_N3 ((EDIM*EDIM)/4)
#define CVT_N4 ((TLEN*TLEN)/4)
__global__ void cvt_kernel(const float4* __restrict__ q,
                           const float4* __restrict__ wi,
                           const float4* __restrict__ wo,
                           const float4* __restrict__ mk)
{
    int i = blockIdx.x * blockDim.x + threadIdx.x;
    float4 v;
    __half2* dst;
    if (i < CVT_N1)                    { v = q[i];                 dst = (__half2*)g_qin   + i*2; }
    else if (i < CVT_N1+CVT_N2)        { v = wi[i-CVT_N1];         dst = (__half2*)g_winh  + (i-CVT_N1)*2; }
    else if (i < CVT_N1+CVT_N2+CVT_N3) { v = wo[i-CVT_N1-CVT_N2];  dst = (__half2*)g_wouth + (i-CVT_N1-CVT_N2)*2; }
    else if (i < CVT_N1+CVT_N2+CVT_N3+CVT_N4) {
        v = mk[i-CVT_N1-CVT_N2-CVT_N3];
        if (v.x != 0.f || v.y != 0.f || v.z != 0.f || v.w != 0.f)
            atomicOr(&g_mask_nz, 1);   // idempotent; static init = 0
        v.x *= L2E; v.y *= L2E; v.z *= L2E; v.w *= L2E;
        dst = (__half2*)g_maskh + (i-CVT_N1-CVT_N2-CVT_N3)*2;
    }
    else return;
    dst[0] = __floats2half2_rn(v.x, v.y);
    dst[1] = __floats2half2_rn(v.z, v.w);
}

// ======================= hgemm mainloop (shared by both GEMMs) =======================
// BM=128, BN=128, BK=64, 128 threads (4 warps in 2x2), warp tile 64x64.
#define GST 72
#define G_AB_HALVES 9216                 // 128*72
#define HGEMM_SMEM (4*G_AB_HALVES*2)     // 73728 B

// computes acc[4][8][4] for this thread; shared by both epilogues
#define HGEMM_MAINLOOP(A_, W_, K_)                                                        \
    const int tid  = threadIdx.x;                                                         \
    const int w    = tid >> 5;                                                            \
    const int lane = tid & 31;                                                            \
    const int g    = lane >> 2;                                                           \
    const int tig  = lane & 3;                                                            \
    const int wm   = w >> 1;                                                              \
    const int wn   = w & 1;                                                               \
    const int m0   = blockIdx.y * 128;                                                    \
    const int n0   = blockIdx.x * 128;                                                    \
    const uint32_t sb = smem_u32(hs);                                                     \
    const int mi = lane >> 3, ri = lane & 7;                                              \
    const int a_row = (mi & 1) * 8 + ri;                                                  \
    const int a_kof = (mi >> 1) * 8;                                                      \
    const int b_row = (mi >> 1) * 8 + ri;                                                 \
    const int b_kof = (mi & 1) * 8;                                                       \
    const uint32_t a_lane_off = (uint32_t)(((wm * 64 + a_row) * GST + a_kof) * 2);        \
    const uint32_t b_lane_off = (uint32_t)(((wn * 64 + b_row) * GST + b_kof) * 2);        \
    auto cp_tileAB = [&](int kt, int buf) {                                               \
        uint32_t adst = sb + (buf * G_AB_HALVES) * 2;                                     \
        uint32_t bdst = sb + ((2 * G_AB_HALVES) + buf * G_AB_HALVES) * 2;                 \
        const __half* as = (A_) + (size_t)m0 * (K_) + kt;                                 \
        const __half* ws = (W_) + (size_t)n0 * (K_) + kt;                                 \
        _Pragma("unroll")                                                                 \
        for (int j = 0; j < 8; j++) {                                                     \
            int lin = tid + 128 * j;                                                      \
            int row = lin >> 3, c = lin & 7;                                              \
            cp16(adst + (row * GST + c * 8) * 2, as + (size_t)row * (K_) + c * 8);        \
            cp16(bdst + (row * GST + c * 8) * 2, ws + (size_t)row * (K_) + c * 8);        \
        }                                                                                 \
    };                                                                                    \
    cp_tileAB(0, 0);                                                                      \
    CP_COMMIT(); CP_WAIT0();                                                              \
    __syncthreads();                                                                      \
    float acc[4][8][4];                                                                   \
    _Pragma("unroll")                                                                     \
    for (int f = 0; f < 4; f++)                                                           \
        _Pragma("unroll")                                                                 \
        for (int nt = 0; nt < 8; nt++)                                                    \
            _Pragma("unroll")                                                             \
            for (int i = 0; i < 4; i++) acc[f][nt][i] = 0.f;                              \
    const int nsteps = (K_) / 64;                                                         \
    for (int s = 0; s < nsteps; s++) {                                                    \
        const int cur = s & 1;                                                            \
        if (s + 1 < nsteps) { cp_tileAB((s + 1) * 64, cur ^ 1); CP_COMMIT(); }            \
        const uint32_t a_s = sb + (cur * G_AB_HALVES) * 2 + a_lane_off;                   \
        const uint32_t b_s = sb + ((2 * G_AB_HALVES) + cur * G_AB_HALVES) * 2 + b_lane_off;\
        _Pragma("unroll")                                                                 \
        for (int kk = 0; kk < 4; kk++) {                                                  \
            uint32_t afr[4][4];                                                           \
            _Pragma("unroll")                                                             \
            for (int f = 0; f < 4; f++)                                                   \
                LDSM_X4(afr[f][0], afr[f][1], afr[f][2], afr[f][3],                       \
                        a_s + (f * 16 * GST + kk * 16) * 2);                              \
            _Pragma("unroll")                                                             \
            for (int ntp = 0; ntp < 4; ntp++) {                                           \
                uint32_t b0a, b1a, b0b, b1b;                                              \
                LDSM_X4(b0a, b1a, b0b, b1b, b_s + (ntp * 16 * GST + kk * 16) * 2);        \
                _Pragma("unroll")                                                         \
                for (int f = 0; f < 4; f++) {                                             \
                    mma_f16(acc[f][2*ntp],   afr[f], b0a, b1a);                           \
                    mma_f16(acc[f][2*ntp+1], afr[f], b0b, b1b);                           \
                }                                                                         \
            }                                                                             \
        }                                                                                 \
        CP_WAIT0();                                                                       \
        __syncthreads();                                                                  \
    }

// ---------------- GEMM 1: in-projection with FUSED bias + RoPE + QKV split ----------------
// Each 128-col n-tile lies wholly inside q (tiles 0-5), k (6-11) or v (12-17).
__global__ __launch_bounds__(128, 2) void hgemm_rope(
    const __half* __restrict__ A, const __half* __restrict__ W,
    const float* __restrict__ bias)
{
    extern __shared__ __half hs[];
    HGEMM_MAINLOOP(A, W, EDIM)

    const int region = n0 / EDIM;          // 0=q, 1=k, 2=v (uniform per CTA)
    const float qsc = 0.125f * L2E;

    #pragma unroll
    for (int f = 0; f < 4; f++) {
        int r0 = m0 + wm * 64 + f * 16 + g;        // global row (t*BSZ + b)
        int ta = r0 >> 2, ba = r0 & 3;
        int tb = (r0 + 8) >> 2;                    // (r0+8)&3 == ba
        #pragma unroll
        for (int nt = 0; nt < 8; nt++) {
            int gcol = n0 + wn * 64 + nt * 8 + 2 * tig;   // even
            float bx = bias[gcol], by = bias[gcol + 1];
            float x0 = acc[f][nt][0] + bx, x1 = acc[f][nt][1] + by;   // row r0
            float x2 = acc[f][nt][2] + bx, x3 = acc[f][nt][3] + by;   // row r0+8
            int c = gcol - region * EDIM;           // 0..766 within region
            int h = c >> 6, d = c & 63, j = d >> 1;
            size_t oa = ((size_t)(ba * NH + h) * TLEN + ta) * HD + d;
            size_t ob = ((size_t)(ba * NH + h) * TLEN + tb) * HD + d;
            if (region == 2) {
                *(__half2*)(g_vh + oa) = __floats2half2_rn(x0, x1);
                *(__half2*)(g_vh + ob) = __floats2half2_rn(x2, x3);
            } else {
                float sa, ca, sb2, cb;
                sincosf((float)((double)ta * ROPE_INVF[j]), &sa, &ca);
                sincosf((float)((double)tb * ROPE_INVF[j]), &sb2, &cb);
                float y0 = x0 * ca - x1 * sa, y1 = x1 * ca + x0 * sa;
                float y2 = x2 * cb - x3 * sb2, y3 = x3 * cb + x2 * sb2;
                if (region == 0) {
                    *(__half2*)(g_qh + oa) = __floats2half2_rn(y0 * qsc, y1 * qsc);
                    *(__half2*)(g_qh + ob) = __floats2half2_rn(y2 * qsc, y3 * qsc);
                } else {
                    *(__half2*)(g_kh + oa) = __floats2half2_rn(y0, y1);
                    *(__half2*)(g_kh + ob) = __floats2half2_rn(y2, y3);
                }
            }
        }
    }
}

// ---------------- GEMM 2: out-projection, plain bias epilogue ----------------
__global__ __launch_bounds__(128, 2) void hgemm_bias(
    const __half* __restrict__ A, const __half* __restrict__ W,
    const float* __restrict__ bias, float* __restrict__ C,
    int N, int K)
{
    extern __shared__ __half hs[];
    HGEMM_MAINLOOP(A, W, K)

    #pragma unroll
    for (int f = 0; f < 4; f++) {
        int r0 = m0 + wm * 64 + f * 16 + g;
        #pragma unroll
        for (int nt = 0; nt < 8; nt++) {
            int c = n0 + wn * 64 + nt * 8 + 2 * tig;
            float bx = bias[c], by = bias[c + 1];
            *(float2*)(C + (size_t)r0 * N + c)       = make_float2(acc[f][nt][0] + bx, acc[f][nt][1] + by);
            *(float2*)(C + (size_t)(r0 + 8) * N + c) = make_float2(acc[f][nt][2] + bx, acc[f][nt][3] + by);
        }
    }
}

// ---------------- fp16 mma flash attention (warp-M=32, f16x2 softmax, LDSM.trans V) ----------------
#define FQ  0
#define FK0 9216
#define FK1 13824
#define FV0 18432
#define FV1 23040
#define FLASH_SMEM (27648*2)   // 55296 B

__global__ __launch_bounds__(128, 3) void flash_h_kernel()
{
    extern __shared__ __half hs[];
    const int tid  = threadIdx.x;
    const int w    = tid >> 5;
    const int lane = tid & 31;
    const int g    = lane >> 2;
    const int tig  = lane & 3;
    const int bh   = blockIdx.y;
    const int qt   = blockIdx.x;
    const uint32_t sb = smem_u32(hs);

    const bool mnz = (g_mask_nz != 0);

    const int qbase = qt * 128 + w * 32 + g;

    const __half* qg = g_qh + (size_t)bh * TLEN * HD;
    const __half* kg = g_kh + (size_t)bh * TLEN * HD;
    const __half* vg = g_vh + (size_t)bh * TLEN * HD;

    const int mi = lane >> 3, ri = lane & 7;
    const int b_row = (mi >> 1) * 8 + ri;
    const int b_kof = (mi & 1) * 8;
    const uint32_t b_lane_off = (uint32_t)((b_row * GST + b_kof) * 2);
    const int v_row = (mi & 1) * 8 + ri;
    const int v_kof = (mi >> 1) * 8;
    const uint32_t v_lane_off = (uint32_t)((v_row * GST + v_kof) * 2);

    // ---- prolog: Q tile (128x64) + K/V tile 0
    #pragma unroll
    for (int j = 0; j < 8; j++) {
        int lin = tid + 128 * j;
        int row = lin >> 3, c = lin & 7;
        cp16(sb + (FQ + row * GST + c * 8) * 2, qg + (size_t)(qt * 128 + row) * HD + c * 8);
    }
    #pragma unroll
    for (int j = 0; j < 4; j++) {
        int lin = tid + 128 * j;
        int row = lin >> 3, c = lin & 7;
        cp16(sb + (FK0 + row * GST + c * 8) * 2, kg + (size_t)row * HD + c * 8);
        cp16(sb + (FV0 + row * GST + c * 8) * 2, vg + (size_t)row * HD + c * 8);
    }
    CP_COMMIT(); CP_WAIT0();
    __syncthreads();

    // ---- Q A-frags (resident): 2 m16 frags per warp
    uint32_t qa[2][4][4];
    {
        const uint32_t* q32 = (const uint32_t*)hs;
        #pragma unroll
        for (int f = 0; f < 2; f++) {
            int r0 = w * 32 + f * 16 + g, r1 = r0 + 8;
            #pragma unroll
            for (int ks = 0; ks < 4; ks++) {
                const uint32_t* p0 = q32 + r0 * 36 + ks * 8 + tig;
                const uint32_t* p1 = q32 + r1 * 36 + ks * 8 + tig;
                qa[f][ks][0] = p0[0]; qa[f][ks][1] = p1[0];
                qa[f][ks][2] = p0[4]; qa[f][ks][3] = p1[4];
            }
        }
    }

    float oacc[2][8][4];
    #pragma unroll
    for (int f = 0; f < 2; f++)
        #pragma unroll
        for (int nt = 0; nt < 8; nt++)
            #pragma unroll
            for (int i = 0; i < 4; i++) oacc[f][nt][i] = 0.f;
    float lsum[4] = {0.f, 0.f, 0.f, 0.f};

    const uint32_t* mrb = (const uint32_t*)(g_maskh + (size_t)qbase * TLEN);
    const int RW = TLEN / 2;

    for (int it = 0; it < 32; it++) {
        const int cur = it & 1;

        if (it < 31) {
            const __half* ksrc = kg + (size_t)(it + 1) * 64 * HD;
            const __half* vsrc = vg + (size_t)(it + 1) * 64 * HD;
            uint32_t kdst = sb + ((cur ? FK0 : FK1)) * 2;
            uint32_t vdst = sb + ((cur ? FV0 : FV1)) * 2;
            #pragma unroll
            for (int j = 0; j < 4; j++) {
                int lin = tid + 128 * j;
                int row = lin >> 3, c = lin & 7;
                cp16(kdst + (row * GST + c * 8) * 2, ksrc + (size_t)row * HD + c * 8);
                cp16(vdst + (row * GST + c * 8) * 2, vsrc + (size_t)row * HD + c * 8);
            }
            CP_COMMIT();
        }

        const uint32_t kb = sb + ((cur ? FK1 : FK0)) * 2 + b_lane_off;
        const uint32_t vb = sb + ((cur ? FV1 : FV0)) * 2 + v_lane_off;
        const int mo = it * 32;

        uint32_t lacc[4] = {0u, 0u, 0u, 0u};

        #pragma unroll
        for (int np = 0; np < 4; np++) {
            float s[2][2][4];
            #pragma unroll
            for (int f = 0; f < 2; f++)
                #pragma unroll
                for (int n = 0; n < 2; n++)
                    #pragma unroll
                    for (int i = 0; i < 4; i++) s[f][n][i] = 0.f;
            #pragma unroll
            for (int ks = 0; ks < 4; ks++) {
                uint32_t b0a, b1a, b0b, b1b;
                LDSM_X4(b0a, b1a, b0b, b1b, kb + (np * 16 * GST + ks * 16) * 2);
                mma_f16(s[0][0], qa[0][ks], b0a, b1a);
                mma_f16(s[0][1], qa[0][ks], b0b, b1b);
                mma_f16(s[1][0], qa[1][ks], b0a, b1a);
                mma_f16(s[1][1], qa[1][ks], b0b, b1b);
            }

            uint32_t pa[2][4];
            #pragma unroll
            for (int f = 0; f < 2; f++) {
                uint32_t x0 = cvt_h2(s[f][0][0], s[f][0][1]);
                uint32_t x1 = cvt_h2(s[f][0][2], s[f][0][3]);
                uint32_t x2 = cvt_h2(s[f][1][0], s[f][1][1]);
                uint32_t x3 = cvt_h2(s[f][1][2], s[f][1][3]);
                if (mnz) {
                    const uint32_t* m0p = mrb + (size_t)(f * 16) * RW + mo;
                    const uint32_t* m1p = mrb + (size_t)(f * 16 + 8) * RW + mo;
                    x0 = hadd2u(x0, __ldg(m0p + (2*np) * 4 + tig));
                    x1 = hadd2u(x1, __ldg(m1p + (2*np) * 4 + tig));
                    x2 = hadd2u(x2, __ldg(m0p + (2*np+1) * 4 + tig));
                    x3 = hadd2u(x3, __ldg(m1p + (2*np+1) * 4 + tig));
                }
                pa[f][0] = ex2_h2(x0);
                pa[f][1] = ex2_h2(x1);
                pa[f][2] = ex2_h2(x2);
                pa[f][3] = ex2_h2(x3);
                lacc[2*f]   = hadd2u(lacc[2*f],   hadd2u(pa[f][0], pa[f][2]));
                lacc[2*f+1] = hadd2u(lacc[2*f+1], hadd2u(pa[f][1], pa[f][3]));
            }

            #pragma unroll
            for (int ntp = 0; ntp < 4; ntp++) {
                uint32_t b0a, b1a, b0b, b1b;
                LDSM_X4T(b0a, b1a, b0b, b1b, vb + (np * 16 * GST + ntp * 16) * 2);
                mma_f16(oacc[0][2*ntp],   pa[0], b0a, b1a);
                mma_f16(oacc[0][2*ntp+1], pa[0], b0b, b1b);
                mma_f16(oacc[1][2*ntp],   pa[1], b0a, b1a);
                mma_f16(oacc[1][2*ntp+1], pa[1], b0b, b1b);
            }
        }

        #pragma unroll
        for (int r = 0; r < 4; r++) {
            float2 f2 = __half22float2(*(__half2*)&lacc[r]);
            lsum[r] += f2.x + f2.y;
        }

        CP_WAIT0();
        __syncthreads();
    }

    #pragma unroll
    for (int r = 0; r < 4; r++) {
        lsum[r] += __shfl_xor_sync(0xffffffffu, lsum[r], 1);
        lsum[r] += __shfl_xor_sync(0xffffffffu, lsum[r], 2);
    }
    int b = bh / NH, h = bh % NH;
    #pragma unroll
    for (int f = 0; f < 2; f++) {
        float inv0 = 1.f / lsum[2*f];
        float inv1 = 1.f / lsum[2*f+1];
        int r0 = qbase + f * 16;
        __half* o0 = g_attnh + ((size_t)r0 * BSZ + b) * EDIM + h * HD;
        __half* o1 = g_attnh + ((size_t)(r0 + 8) * BSZ + b) * EDIM + h * HD;
        #pragma unroll
        for (int nt = 0; nt < 8; nt++) {
            int c = nt * 8 + 2 * tig;
            *(__half2*)(o0 + c) = __floats2half2_rn(oacc[f][nt][0] * inv0, oacc[f][nt][1] * inv0);
            *(__half2*)(o1 + c) = __floats2half2_rn(oacc[f][nt][2] * inv1, oacc[f][nt][3] * inv1);
        }
    }
}

// ---------------- launch ----------------
extern "C" void kernel_launch(void* const* d_in, const int* in_sizes, int n_in,
                              void* d_out, int out_size)
{
    const float* query = (const float*)d_in[0];
    const float* mask  = (const float*)d_in[1];
    const float* win   = (const float*)d_in[2];
    const float* bin   = (const float*)d_in[3];
    const float* wout  = (const float*)d_in[4];
    const float* bout  = (const float*)d_in[5];
    float* out = (float*)d_out;

    void* p;
    cudaGetSymbolAddress(&p, g_qin);    __half* qin = (__half*)p;
    cudaGetSymbolAddress(&p, g_winh);   __half* winh = (__half*)p;
    cudaGetSymbolAddress(&p, g_wouth);  __half* wouth = (__half*)p;
    cudaGetSymbolAddress(&p, g_attnh);  __half* attnh = (__half*)p;

    static bool attr_set = false;
    if (!attr_set) {
        cudaFuncSetAttribute(hgemm_rope,
                             cudaFuncAttributeMaxDynamicSharedMemorySize, HGEMM_SMEM);
        cudaFuncSetAttribute(hgemm_bias,
                             cudaFuncAttributeMaxDynamicSharedMemorySize, HGEMM_SMEM);
        cudaFuncSetAttribute(flash_h_kernel,
                             cudaFuncAttributeMaxDynamicSharedMemorySize, FLASH_SMEM);
        attr_set = true;
    }

    // 0) convert inputs to fp16 (query, weights, mask*log2e); sets g_mask_nz if needed
    int cvt_total = CVT_N1 + CVT_N2 + CVT_N3 + CVT_N4;
    cvt_kernel<<<(cvt_total + 255) / 256, 256>>>((const float4*)query,
                                                 (const float4*)win,
                                                 (const float4*)wout,
                                                 (const float4*)mask);

    // 1) in-projection with fused bias + RoPE + QKV split -> g_qh/g_kh/g_vh (fp16)
    dim3 g1(E3 / 128, (TLEN * BSZ) / 128);
    hgemm_rope<<<g1, 128, HGEMM_SMEM>>>(qin, winh, bin);

    // 2) flash attention
    dim3 gf(TLEN / 128, BSZ * NH);
    flash_h_kernel<<<gf, 128, FLASH_SMEM>>>();

    // 3) out-projection
    dim3 g2(EDIM / 128, (TLEN * BSZ) / 128);
    hgemm_bias<<<g2, 128, HGEMM_SMEM>>>(attnh, wouth, bout, out, EDIM, EDIM);
}

// round 16
// speedup vs baseline: 1.1270x; 1.1270x over previous
#include <cuda_runtime.h>
#include <cuda_fp16.h>
#include <math.h>
#include <stdint.h>

#define TLEN  2048
#define BSZ   4
#define EDIM  768
#define NH    12
#define HD    64
#define E3    (3*EDIM)
#define L2E   1.4426950408889634f

// ---------------- scratch (no allocation allowed) ----------------
__device__ __half g_qin [TLEN*BSZ*EDIM];        // query fp16
__device__ __half g_winh[E3*EDIM];              // in_proj_weight fp16
__device__ __half g_wouth[EDIM*EDIM];           // out_proj_weight fp16
__device__ __half g_maskh[TLEN*TLEN];           // attn_mask * log2(e), fp16
__device__ __half g_qh[BSZ*NH*TLEN*HD];         // [bh][t][d], RoPE'd, pre-scaled log2e/8
__device__ __half g_kh[BSZ*NH*TLEN*HD];         // [bh][t][d], RoPE'd
__device__ __half g_vh[BSZ*NH*TLEN*HD];         // [bh][t][d]
__device__ __half g_attnh[TLEN*BSZ*EDIM];       // [T*B, E] fp16
__device__ float2 g_rope[TLEN*32];              // (cos, sin) per (t, j)  512 KB
__device__ int    g_mask_nz;                    // static 0; set if mask nonzero (idempotent)

// 10000^(-j/32) = 10^(-j/8), exact double literals
__device__ const double ROPE_INVF[32] = {
    1.0,
    0.74989420933245582, 0.56234132519034907, 0.42169650342858224,
    0.31622776601683794, 0.23713737056616552, 0.17782794100389228,
    0.13335214321633241,
    0.1,
    0.074989420933245582, 0.056234132519034907, 0.042169650342858224,
    0.031622776601683794, 0.023713737056616552, 0.017782794100389228,
    0.013335214321633241,
    0.01,
    0.0074989420933245582, 0.0056234132519034907, 0.0042169650342858224,
    0.0031622776601683794, 0.0023713737056616552, 0.0017782794100389228,
    0.0013335214321633241,
    0.001,
    0.00074989420933245582, 0.00056234132519034907, 0.00042169650342858224,
    0.00031622776601683794, 0.00023713737056616552, 0.00017782794100389228,
    0.00013335214321633241
};

// ======================= helpers =======================
__device__ __forceinline__ uint32_t smem_u32(const void* p) {
    uint32_t a;
    asm("{ .reg .u64 t; cvta.to.shared.u64 t, %1; cvt.u32.u64 %0, t; }" : "=r"(a) : "l"(p));
    return a;
}
__device__ __forceinline__ void cp16(uint32_t dst, const void* src) {
    asm volatile("cp.async.cg.shared.global [%0], [%1], 16;" :: "r"(dst), "l"(src));
}
#define CP_COMMIT() asm volatile("cp.async.commit_group;" ::: "memory")
#define CP_WAIT0()  asm volatile("cp.async.wait_group 0;" ::: "memory")

#define LDSM_X4(r0, r1, r2, r3, addr) \
    asm volatile("ldmatrix.sync.aligned.m8n8.x4.shared.b16 {%0,%1,%2,%3}, [%4];" \
        : "=r"(r0), "=r"(r1), "=r"(r2), "=r"(r3) : "r"(addr))
#define LDSM_X4T(r0, r1, r2, r3, addr) \
    asm volatile("ldmatrix.sync.aligned.m8n8.x4.trans.shared.b16 {%0,%1,%2,%3}, [%4];" \
        : "=r"(r0), "=r"(r1), "=r"(r2), "=r"(r3) : "r"(addr))

__device__ __forceinline__ void mma_f16(float c[4], const uint32_t a[4],
                                        uint32_t b0, uint32_t b1) {
    asm volatile(
        "mma.sync.aligned.m16n8k16.row.col.f32.f16.f16.f32 "
        "{%0,%1,%2,%3}, {%4,%5,%6,%7}, {%8,%9}, {%0,%1,%2,%3};\n"
        : "+f"(c[0]), "+f"(c[1]), "+f"(c[2]), "+f"(c[3])
        : "r"(a[0]), "r"(a[1]), "r"(a[2]), "r"(a[3]), "r"(b0), "r"(b1));
}
__device__ __forceinline__ uint32_t cvt_h2(float lo, float hi) {
    uint32_t r;
    asm("cvt.rn.f16x2.f32 %0, %2, %1;" : "=r"(r) : "f"(lo), "f"(hi));
    return r;
}
__device__ __forceinline__ uint32_t hadd2u(uint32_t a, uint32_t b) {
    uint32_t r;
    asm("add.rn.f16x2 %0, %1, %2;" : "=r"(r) : "r"(a), "r"(b));
    return r;
}
__device__ __forceinline__ uint32_t ex2_h2(uint32_t x) {
    uint32_t r;
    asm("ex2.approx.f16x2 %0, %1;" : "=r"(r) : "r"(x));
    return r;
}

// ---------------- rope table init ----------------
__global__ void rope_tab_kernel() {
    int idx = blockIdx.x * blockDim.x + threadIdx.x;
    if (idx >= TLEN * 32) return;
    int t = idx >> 5, j = idx & 31;
    float s, c;
    sincosf((float)((double)t * ROPE_INVF[j]), &s, &c);
    g_rope[idx] = make_float2(c, s);
}

// ---------------- fp32 -> fp16 convert (query, win, wout, mask*log2e) ----------------
#define CVT_N1 ((TLEN*BSZ*EDIM)/4)
#define CVT_N2 ((E3*EDIM)/4)
#define CVT_N3 ((EDIM*EDIM)/4)
#define CVT_N4 ((TLEN*TLEN)/4)
__global__ void cvt_kernel(const float4* __restrict__ q,
                           const float4* __restrict__ wi,
                           const float4* __restrict__ wo,
                           const float4* __restrict__ mk)
{
    int i = blockIdx.x * blockDim.x + threadIdx.x;
    float4 v;
    __half2* dst;
    if (i < CVT_N1)                    { v = q[i];                 dst = (__half2*)g_qin   + i*2; }
    else if (i < CVT_N1+CVT_N2)        { v = wi[i-CVT_N1];         dst = (__half2*)g_winh  + (i-CVT_N1)*2; }
    else if (i < CVT_N1+CVT_N2+CVT_N3) { v = wo[i-CVT_N1-CVT_N2];  dst = (__half2*)g_wouth + (i-CVT_N1-CVT_N2)*2; }
    else if (i < CVT_N1+CVT_N2+CVT_N3+CVT_N4) {
        v = mk[i-CVT_N1-CVT_N2-CVT_N3];
        if (v.x != 0.f || v.y != 0.f || v.z != 0.f || v.w != 0.f)
            atomicOr(&g_mask_nz, 1);   // idempotent; static init = 0
        v.x *= L2E; v.y *= L2E; v.z *= L2E; v.w *= L2E;
        dst = (__half2*)g_maskh + (i-CVT_N1-CVT_N2-CVT_N3)*2;
    }
    else return;
    dst[0] = __floats2half2_rn(v.x, v.y);
    dst[1] = __floats2half2_rn(v.z, v.w);
}

// ======================= hgemm mainloop (256 threads, warp tile 32x64) =======================
#define GST 72
#define G_AB_HALVES 9216                 // 128*72
#define HGEMM_SMEM (4*G_AB_HALVES*2)     // 73728 B

#define HGEMM_MAINLOOP(A_, W_, K_)                                                        \
    const int tid  = threadIdx.x;                                                         \
    const int w    = tid >> 5;                                                            \
    const int lane = tid & 31;                                                            \
    const int g    = lane >> 2;                                                           \
    const int tig  = lane & 3;                                                            \
    const int wm   = w >> 1;                                                              \
    const int wn   = w & 1;                                                               \
    const int m0   = blockIdx.y * 128;                                                    \
    const int n0   = blockIdx.x * 128;                                                    \
    const uint32_t sb = smem_u32(hs);                                                     \
    const int mi = lane >> 3, ri = lane & 7;                                              \
    const int a_row = (mi & 1) * 8 + ri;                                                  \
    const int a_kof = (mi >> 1) * 8;                                                      \
    const int b_row = (mi >> 1) * 8 + ri;                                                 \
    const int b_kof = (mi & 1) * 8;                                                       \
    const uint32_t a_lane_off = (uint32_t)(((wm * 32 + a_row) * GST + a_kof) * 2);        \
    const uint32_t b_lane_off = (uint32_t)(((wn * 64 + b_row) * GST + b_kof) * 2);        \
    auto cp_tileAB = [&](int kt, int buf) {                                               \
        uint32_t adst = sb + (buf * G_AB_HALVES) * 2;                                     \
        uint32_t bdst = sb + ((2 * G_AB_HALVES) + buf * G_AB_HALVES) * 2;                 \
        const __half* as = (A_) + (size_t)m0 * (K_) + kt;                                 \
        const __half* ws = (W_) + (size_t)n0 * (K_) + kt;                                 \
        _Pragma("unroll")                                                                 \
        for (int j = 0; j < 4; j++) {                                                     \
            int lin = tid + 256 * j;                                                      \
            int row = lin >> 3, c = lin & 7;                                              \
            cp16(adst + (row * GST + c * 8) * 2, as + (size_t)row * (K_) + c * 8);        \
            cp16(bdst + (row * GST + c * 8) * 2, ws + (size_t)row * (K_) + c * 8);        \
        }                                                                                 \
    };                                                                                    \
    cp_tileAB(0, 0);                                                                      \
    CP_COMMIT(); CP_WAIT0();                                                              \
    __syncthreads();                                                                      \
    float acc[2][8][4];                                                                   \
    _Pragma("unroll")                                                                     \
    for (int f = 0; f < 2; f++)                                                           \
        _Pragma("unroll")                                                                 \
        for (int nt = 0; nt < 8; nt++)                                                    \
            _Pragma("unroll")                                                             \
            for (int i = 0; i < 4; i++) acc[f][nt][i] = 0.f;                              \
    const int nsteps = (K_) / 64;                                                         \
    for (int s = 0; s < nsteps; s++) {                                                    \
        const int cur = s & 1;                                                            \
        if (s + 1 < nsteps) { cp_tileAB((s + 1) * 64, cur ^ 1); CP_COMMIT(); }            \
        const uint32_t a_s = sb + (cur * G_AB_HALVES) * 2 + a_lane_off;                   \
        const uint32_t b_s = sb + ((2 * G_AB_HALVES) + cur * G_AB_HALVES) * 2 + b_lane_off;\
        _Pragma("unroll")                                                                 \
        for (int kk = 0; kk < 4; kk++) {                                                  \
            uint32_t afr[2][4];                                                           \
            _Pragma("unroll")                                                             \
            for (int f = 0; f < 2; f++)                                                   \
                LDSM_X4(afr[f][0], afr[f][1], afr[f][2], afr[f][3],                       \
                        a_s + (f * 16 * GST + kk * 16) * 2);                              \
            _Pragma("unroll")                                                             \
            for (int ntp = 0; ntp < 4; ntp++) {                                           \
                uint32_t b0a, b1a, b0b, b1b;                                              \
                LDSM_X4(b0a, b1a, b0b, b1b, b_s + (ntp * 16 * GST + kk * 16) * 2);        \
                mma_f16(acc[0][2*ntp],   afr[0], b0a, b1a);                               \
                mma_f16(acc[1][2*ntp],   afr[1], b0a, b1a);                               \
                mma_f16(acc[0][2*ntp+1], afr[0], b0b, b1b);                               \
                mma_f16(acc[1][2*ntp+1], afr[1], b0b, b1b);                               \
            }                                                                             \
        }                                                                                 \
        CP_WAIT0();                                                                       \
        __syncthreads();                                                                  \
    }

// ---------------- GEMM 1: in-projection, FUSED bias + table-RoPE + QKV split ----------------
__global__ __launch_bounds__(256, 2) void hgemm_rope(
    const __half* __restrict__ A, const __half* __restrict__ W,
    const float* __restrict__ bias)
{
    extern __shared__ __half hs[];
    HGEMM_MAINLOOP(A, W, EDIM)

    const int region = n0 / EDIM;          // 0=q, 1=k, 2=v (uniform per CTA)
    const float qsc = 0.125f * L2E;

    #pragma unroll
    for (int f = 0; f < 2; f++) {
        int r0 = m0 + wm * 32 + f * 16 + g;        // global row (t*BSZ + b)
        int ta = r0 >> 2, ba = r0 & 3;
        int tb = (r0 + 8) >> 2;                    // (r0+8)&3 == ba
        #pragma unroll
        for (int nt = 0; nt < 8; nt++) {
            int gcol = n0 + wn * 64 + nt * 8 + 2 * tig;
            float bx = bias[gcol], by = bias[gcol + 1];
            float x0 = acc[f][nt][0] + bx, x1 = acc[f][nt][1] + by;   // row r0
            float x2 = acc[f][nt][2] + bx, x3 = acc[f][nt][3] + by;   // row r0+8
            int c = gcol - region * EDIM;
            int h = c >> 6, d = c & 63, j = d >> 1;
            size_t oa = ((size_t)(ba * NH + h) * TLEN + ta) * HD + d;
            size_t ob = ((size_t)(ba * NH + h) * TLEN + tb) * HD + d;
            if (region == 2) {
                *(__half2*)(g_vh + oa) = __floats2half2_rn(x0, x1);
                *(__half2*)(g_vh + ob) = __floats2half2_rn(x2, x3);
            } else {
                float2 csa = g_rope[ta * 32 + j];
                float2 csb = g_rope[tb * 32 + j];
                float y0 = x0 * csa.x - x1 * csa.y, y1 = x1 * csa.x + x0 * csa.y;
                float y2 = x2 * csb.x - x3 * csb.y, y3 = x3 * csb.x + x2 * csb.y;
                if (region == 0) {
                    *(__half2*)(g_qh + oa) = __floats2half2_rn(y0 * qsc, y1 * qsc);
                    *(__half2*)(g_qh + ob) = __floats2half2_rn(y2 * qsc, y3 * qsc);
                } else {
                    *(__half2*)(g_kh + oa) = __floats2half2_rn(y0, y1);
                    *(__half2*)(g_kh + ob) = __floats2half2_rn(y2, y3);
                }
            }
        }
    }
}

// ---------------- GEMM 2: out-projection, plain bias epilogue ----------------
__global__ __launch_bounds__(256, 2) void hgemm_bias(
    const __half* __restrict__ A, const __half* __restrict__ W,
    const float* __restrict__ bias, float* __restrict__ C,
    int N, int K)
{
    extern __shared__ __half hs[];
    HGEMM_MAINLOOP(A, W, K)

    #pragma unroll
    for (int f = 0; f < 2; f++) {
        int r0 = m0 + wm * 32 + f * 16 + g;
        #pragma unroll
        for (int nt = 0; nt < 8; nt++) {
            int c = n0 + wn * 64 + nt * 8 + 2 * tig;
            float bx = bias[c], by = bias[c + 1];
            *(float2*)(C + (size_t)r0 * N + c)       = make_float2(acc[f][nt][0] + bx, acc[f][nt][1] + by);
            *(float2*)(C + (size_t)(r0 + 8) * N + c) = make_float2(acc[f][nt][2] + bx, acc[f][nt][3] + by);
        }
    }
}

// ---------------- fp16 mma flash attention (warp-M=32, f16x2 softmax, LDSM.trans V) ----------------
#define FQ  0
#define FK0 9216
#define FK1 13824
#define FV0 18432
#define FV1 23040
#define FLASH_SMEM (27648*2)   // 55296 B

__global__ __launch_bounds__(128, 3) void flash_h_kernel()
{
    extern __shared__ __half hs[];
    const int tid  = threadIdx.x;
    const int w    = tid >> 5;
    const int lane = tid & 31;
    const int g    = lane >> 2;
    const int tig  = lane & 3;
    const int bh   = blockIdx.y;
    const int qt   = blockIdx.x;
    const uint32_t sb = smem_u32(hs);

    const bool mnz = (g_mask_nz != 0);

    const int qbase = qt * 128 + w * 32 + g;

    const __half* qg = g_qh + (size_t)bh * TLEN * HD;
    const __half* kg = g_kh + (size_t)bh * TLEN * HD;
    const __half* vg = g_vh + (size_t)bh * TLEN * HD;

    const int mi = lane >> 3, ri = lane & 7;
    const int b_row = (mi >> 1) * 8 + ri;
    const int b_kof = (mi & 1) * 8;
    const uint32_t b_lane_off = (uint32_t)((b_row * GST + b_kof) * 2);
    const int v_row = (mi & 1) * 8 + ri;
    const int v_kof = (mi >> 1) * 8;
    const uint32_t v_lane_off = (uint32_t)((v_row * GST + v_kof) * 2);

    // ---- prolog: Q tile (128x64) + K/V tile 0
    #pragma unroll
    for (int j = 0; j < 8; j++) {
        int lin = tid + 128 * j;
        int row = lin >> 3, c = lin & 7;
        cp16(sb + (FQ + row * GST + c * 8) * 2, qg + (size_t)(qt * 128 + row) * HD + c * 8);
    }
    #pragma unroll
    for (int j = 0; j < 4; j++) {
        int lin = tid + 128 * j;
        int row = lin >> 3, c = lin & 7;
        cp16(sb + (FK0 + row * GST + c * 8) * 2, kg + (size_t)row * HD + c * 8);
        cp16(sb + (FV0 + row * GST + c * 8) * 2, vg + (size_t)row * HD + c * 8);
    }
    CP_COMMIT(); CP_WAIT0();
    __syncthreads();

    // ---- Q A-frags (resident): 2 m16 frags per warp
    uint32_t qa[2][4][4];
    {
        const uint32_t* q32 = (const uint32_t*)hs;
        #pragma unroll
        for (int f = 0; f < 2; f++) {
            int r0 = w * 32 + f * 16 + g, r1 = r0 + 8;
            #pragma unroll
            for (int ks = 0; ks < 4; ks++) {
                const uint32_t* p0 = q32 + r0 * 36 + ks * 8 + tig;
                const uint32_t* p1 = q32 + r1 * 36 + ks * 8 + tig;
                qa[f][ks][0] = p0[0]; qa[f][ks][1] = p1[0];
                qa[f][ks][2] = p0[4]; qa[f][ks][3] = p1[4];
            }
        }
    }

    float oacc[2][8][4];
    #pragma unroll
    for (int f = 0; f < 2; f++)
        #pragma unroll
        for (int nt = 0; nt < 8; nt++)
            #pragma unroll
            for (int i = 0; i < 4; i++) oacc[f][nt][i] = 0.f;
    float lsum[4] = {0.f, 0.f, 0.f, 0.f};

    const uint32_t* mrb = (const uint32_t*)(g_maskh + (size_t)qbase * TLEN);
    const int RW = TLEN / 2;

    for (int it = 0; it < 32; it++) {
        const int cur = it & 1;

        if (it < 31) {
            const __half* ksrc = kg + (size_t)(it + 1) * 64 * HD;
            const __half* vsrc = vg + (size_t)(it + 1) * 64 * HD;
            uint32_t kdst = sb + ((cur ? FK0 : FK1)) * 2;
            uint32_t vdst = sb + ((cur ? FV0 : FV1)) * 2;
            #pragma unroll
            for (int j = 0; j < 4; j++) {
                int lin = tid + 128 * j;
                int row = lin >> 3, c = lin & 7;
                cp16(kdst + (row * GST + c * 8) * 2, ksrc + (size_t)row * HD + c * 8);
                cp16(vdst + (row * GST + c * 8) * 2, vsrc + (size_t)row * HD + c * 8);
            }
            CP_COMMIT();
        }

        const uint32_t kb = sb + ((cur ? FK1 : FK0)) * 2 + b_lane_off;
        const uint32_t vb = sb + ((cur ? FV1 : FV0)) * 2 + v_lane_off;
        const int mo = it * 32;

        uint32_t lacc[4] = {0u, 0u, 0u, 0u};

        #pragma unroll
        for (int np = 0; np < 4; np++) {
            float s[2][2][4];
            #pragma unroll
            for (int f = 0; f < 2; f++)
                #pragma unroll
                for (int n = 0; n < 2; n++)
                    #pragma unroll
                    for (int i = 0; i < 4; i++) s[f][n][i] = 0.f;
            #pragma unroll
            for (int ks = 0; ks < 4; ks++) {
                uint32_t b0a, b1a, b0b, b1b;
                LDSM_X4(b0a, b1a, b0b, b1b, kb + (np * 16 * GST + ks * 16) * 2);
                mma_f16(s[0][0], qa[0][ks], b0a, b1a);
                mma_f16(s[0][1], qa[0][ks], b0b, b1b);
                mma_f16(s[1][0], qa[1][ks], b0a, b1a);
                mma_f16(s[1][1], qa[1][ks], b0b, b1b);
            }

            uint32_t pa[2][4];
            #pragma unroll
            for (int f = 0; f < 2; f++) {
                uint32_t x0 = cvt_h2(s[f][0][0], s[f][0][1]);
                uint32_t x1 = cvt_h2(s[f][0][2], s[f][0][3]);
                uint32_t x2 = cvt_h2(s[f][1][0], s[f][1][1]);
                uint32_t x3 = cvt_h2(s[f][1][2], s[f][1][3]);
                if (mnz) {
                    const uint32_t* m0p = mrb + (size_t)(f * 16) * RW + mo;
                    const uint32_t* m1p = mrb + (size_t)(f * 16 + 8) * RW + mo;
                    x0 = hadd2u(x0, __ldg(m0p + (2*np) * 4 + tig));
                    x1 = hadd2u(x1, __ldg(m1p + (2*np) * 4 + tig));
                    x2 = hadd2u(x2, __ldg(m0p + (2*np+1) * 4 + tig));
                    x3 = hadd2u(x3, __ldg(m1p + (2*np+1) * 4 + tig));
                }
                pa[f][0] = ex2_h2(x0);
                pa[f][1] = ex2_h2(x1);
                pa[f][2] = ex2_h2(x2);
                pa[f][3] = ex2_h2(x3);
                lacc[2*f]   = hadd2u(lacc[2*f],   hadd2u(pa[f][0], pa[f][2]));
                lacc[2*f+1] = hadd2u(lacc[2*f+1], hadd2u(pa[f][1], pa[f][3]));
            }

            #pragma unroll
            for (int ntp = 0; ntp < 4; ntp++) {
                uint32_t b0a, b1a, b0b, b1b;
                LDSM_X4T(b0a, b1a, b0b, b1b, vb + (np * 16 * GST + ntp * 16) * 2);
                mma_f16(oacc[0][2*ntp],   pa[0], b0a, b1a);
                mma_f16(oacc[0][2*ntp+1], pa[0], b0b, b1b);
                mma_f16(oacc[1][2*ntp],   pa[1], b0a, b1a);
                mma_f16(oacc[1][2*ntp+1], pa[1], b0b, b1b);
            }
        }

        #pragma unroll
        for (int r = 0; r < 4; r++) {
            float2 f2 = __half22float2(*(__half2*)&lacc[r]);
            lsum[r] += f2.x + f2.y;
        }

        CP_WAIT0();
        __syncthreads();
    }

    #pragma unroll
    for (int r = 0; r < 4; r++) {
        lsum[r] += __shfl_xor_sync(0xffffffffu, lsum[r], 1);
        lsum[r] += __shfl_xor_sync(0xffffffffu, lsum[r], 2);
    }
    int b = bh / NH, h = bh % NH;
    #pragma unroll
    for (int f = 0; f < 2; f++) {
        float inv0 = 1.f / lsum[2*f];
        float inv1 = 1.f / lsum[2*f+1];
        int r0 = qbase + f * 16;
        __half* o0 = g_attnh + ((size_t)r0 * BSZ + b) * EDIM + h * HD;
        __half* o1 = g_attnh + ((size_t)(r0 + 8) * BSZ + b) * EDIM + h * HD;
        #pragma unroll
        for (int nt = 0; nt < 8; nt++) {
            int c = nt * 8 + 2 * tig;
            *(__half2*)(o0 + c) = __floats2half2_rn(oacc[f][nt][0] * inv0, oacc[f][nt][1] * inv0);
            *(__half2*)(o1 + c) = __floats2half2_rn(oacc[f][nt][2] * inv1, oacc[f][nt][3] * inv1);
        }
    }
}

// ---------------- launch ----------------
extern "C" void kernel_launch(void* const* d_in, const int* in_sizes, int n_in,
                              void* d_out, int out_size)
{
    const float* query = (const float*)d_in[0];
    const float* mask  = (const float*)d_in[1];
    const float* win   = (const float*)d_in[2];
    const float* bin   = (const float*)d_in[3];
    const float* wout  = (const float*)d_in[4];
    const float* bout  = (const float*)d_in[5];
    float* out = (float*)d_out;

    void* p;
    cudaGetSymbolAddress(&p, g_qin);    __half* qin = (__half*)p;
    cudaGetSymbolAddress(&p, g_winh);   __half* winh = (__half*)p;
    cudaGetSymbolAddress(&p, g_wouth);  __half* wouth = (__half*)p;
    cudaGetSymbolAddress(&p, g_attnh);  __half* attnh = (__half*)p;

    static bool attr_set = false;
    if (!attr_set) {
        cudaFuncSetAttribute(hgemm_rope,
                             cudaFuncAttributeMaxDynamicSharedMemorySize, HGEMM_SMEM);
        cudaFuncSetAttribute(hgemm_bias,
                             cudaFuncAttributeMaxDynamicSharedMemorySize, HGEMM_SMEM);
        cudaFuncSetAttribute(flash_h_kernel,
                             cudaFuncAttributeMaxDynamicSharedMemorySize, FLASH_SMEM);
        attr_set = true;
    }

    // 0a) rope table (cos/sin per (t, j))
    rope_tab_kernel<<<(TLEN * 32 + 255) / 256, 256>>>();
    // 0b) convert inputs to fp16; sets g_mask_nz if mask nonzero
    int cvt_total = CVT_N1 + CVT_N2 + CVT_N3 + CVT_N4;
    cvt_kernel<<<(cvt_total + 255) / 256, 256>>>((const float4*)query,
                                                 (const float4*)win,
                                                 (const float4*)wout,
                                                 (const float4*)mask);

    // 1) in-projection with fused bias + table-RoPE + QKV split -> g_qh/g_kh/g_vh
    dim3 g1(E3 / 128, (TLEN * BSZ) / 128);
    hgemm_rope<<<g1, 256, HGEMM_SMEM>>>(qin, winh, bin);

    // 2) flash attention
    dim3 gf(TLEN / 128, BSZ * NH);
    flash_h_kernel<<<gf, 128, FLASH_SMEM>>>();

    // 3) out-projection
    dim3 g2(EDIM / 128, (TLEN * BSZ) / 128);
    hgemm_bias<<<g2, 256, HGEMM_SMEM>>>(attnh, wouth, bout, out, EDIM, EDIM);
}

// round 17
// speedup vs baseline: 1.1407x; 1.0121x over previous
#include <cuda_runtime.h>
#include <cuda_fp16.h>
#include <math.h>
#include <stdint.h>

#define TLEN  2048
#define BSZ   4
#define EDIM  768
#define NH    12
#define HD    64
#define E3    (3*EDIM)
#define L2E   1.4426950408889634f

// ---------------- scratch (no allocation allowed) ----------------
__device__ __half g_qin [TLEN*BSZ*EDIM];        // query fp16
__device__ __half g_winh[E3*EDIM];              // in_proj_weight fp16
__device__ __half g_wouth[EDIM*EDIM];           // out_proj_weight fp16
__device__ __half g_maskh[TLEN*TLEN];           // attn_mask * log2(e), fp16
__device__ __half g_qh[BSZ*NH*TLEN*HD];         // [bh][t][d], RoPE'd, pre-scaled log2e/8
__device__ __half g_kh[BSZ*NH*TLEN*HD];         // [bh][t][d], RoPE'd
__device__ __half g_vh[BSZ*NH*TLEN*HD];         // [bh][t][d]
__device__ __half g_attnh[TLEN*BSZ*EDIM];       // [T*B, E] fp16
__device__ float2 g_rope[TLEN*32];              // (cos, sin) per (t, j)
__device__ int    g_mask_nz;                    // static 0; set if mask nonzero (idempotent)

// 10000^(-j/32) = 10^(-j/8), exact double literals
__device__ const double ROPE_INVF[32] = {
    1.0,
    0.74989420933245582, 0.56234132519034907, 0.42169650342858224,
    0.31622776601683794, 0.23713737056616552, 0.17782794100389228,
    0.13335214321633241,
    0.1,
    0.074989420933245582, 0.056234132519034907, 0.042169650342858224,
    0.031622776601683794, 0.023713737056616552, 0.017782794100389228,
    0.013335214321633241,
    0.01,
    0.0074989420933245582, 0.0056234132519034907, 0.0042169650342858224,
    0.0031622776601683794, 0.0023713737056616552, 0.0017782794100389228,
    0.0013335214321633241,
    0.001,
    0.00074989420933245582, 0.00056234132519034907, 0.00042169650342858224,
    0.00031622776601683794, 0.00023713737056616552, 0.00017782794100389228,
    0.00013335214321633241
};

// ======================= helpers =======================
__device__ __forceinline__ uint32_t smem_u32(const void* p) {
    uint32_t a;
    asm("{ .reg .u64 t; cvta.to.shared.u64 t, %1; cvt.u32.u64 %0, t; }" : "=r"(a) : "l"(p));
    return a;
}
__device__ __forceinline__ void cp16(uint32_t dst, const void* src) {
    asm volatile("cp.async.cg.shared.global [%0], [%1], 16;" :: "r"(dst), "l"(src));
}
#define CP_COMMIT() asm volatile("cp.async.commit_group;" ::: "memory")
#define CP_WAIT0()  asm volatile("cp.async.wait_group 0;" ::: "memory")

#define LDSM_X4(r0, r1, r2, r3, addr) \
    asm volatile("ldmatrix.sync.aligned.m8n8.x4.shared.b16 {%0,%1,%2,%3}, [%4];" \
        : "=r"(r0), "=r"(r1), "=r"(r2), "=r"(r3) : "r"(addr))
#define LDSM_X4T(r0, r1, r2, r3, addr) \
    asm volatile("ldmatrix.sync.aligned.m8n8.x4.trans.shared.b16 {%0,%1,%2,%3}, [%4];" \
        : "=r"(r0), "=r"(r1), "=r"(r2), "=r"(r3) : "r"(addr))

__device__ __forceinline__ void mma_f16(float c[4], const uint32_t a[4],
                                        uint32_t b0, uint32_t b1) {
    asm volatile(
        "mma.sync.aligned.m16n8k16.row.col.f32.f16.f16.f32 "
        "{%0,%1,%2,%3}, {%4,%5,%6,%7}, {%8,%9}, {%0,%1,%2,%3};\n"
        : "+f"(c[0]), "+f"(c[1]), "+f"(c[2]), "+f"(c[3])
        : "r"(a[0]), "r"(a[1]), "r"(a[2]), "r"(a[3]), "r"(b0), "r"(b1));
}
__device__ __forceinline__ uint32_t cvt_h2(float lo, float hi) {
    uint32_t r;
    asm("cvt.rn.f16x2.f32 %0, %2, %1;" : "=r"(r) : "f"(lo), "f"(hi));
    return r;
}
__device__ __forceinline__ uint32_t hadd2u(uint32_t a, uint32_t b) {
    uint32_t r;
    asm("add.rn.f16x2 %0, %1, %2;" : "=r"(r) : "r"(a), "r"(b));
    return r;
}
__device__ __forceinline__ uint32_t ex2_h2(uint32_t x) {
    uint32_t r;
    asm("ex2.approx.f16x2 %0, %1;" : "=r"(r) : "r"(x));
    return r;
}

// ---------------- fp32 -> fp16 convert + rope table (one kernel) ----------------
#define CVT_N1 ((TLEN*BSZ*EDIM)/4)
#define CVT_N2 ((E3*EDIM)/4)
#define CVT_N3 ((EDIM*EDIM)/4)
#define CVT_N4 ((TLEN*TLEN)/4)
#define CVT_N5 (TLEN*32)
__global__ void cvt_kernel(const float4* __restrict__ q,
                           const float4* __restrict__ wi,
                           const float4* __restrict__ wo,
                           const float4* __restrict__ mk)
{
    int i = blockIdx.x * blockDim.x + threadIdx.x;
    float4 v;
    __half2* dst;
    if (i < CVT_N1)                    { v = q[i];                 dst = (__half2*)g_qin   + i*2; }
    else if (i < CVT_N1+CVT_N2)        { v = wi[i-CVT_N1];         dst = (__half2*)g_winh  + (i-CVT_N1)*2; }
    else if (i < CVT_N1+CVT_N2+CVT_N3) { v = wo[i-CVT_N1-CVT_N2];  dst = (__half2*)g_wouth + (i-CVT_N1-CVT_N2)*2; }
    else if (i < CVT_N1+CVT_N2+CVT_N3+CVT_N4) {
        v = mk[i-CVT_N1-CVT_N2-CVT_N3];
        if (v.x != 0.f || v.y != 0.f || v.z != 0.f || v.w != 0.f)
            atomicOr(&g_mask_nz, 1);   // idempotent; static init = 0
        v.x *= L2E; v.y *= L2E; v.z *= L2E; v.w *= L2E;
        dst = (__half2*)g_maskh + (i-CVT_N1-CVT_N2-CVT_N3)*2;
    }
    else if (i < CVT_N1+CVT_N2+CVT_N3+CVT_N4+CVT_N5) {
        int idx = i - (CVT_N1+CVT_N2+CVT_N3+CVT_N4);
        int t = idx >> 5, j = idx & 31;
        float s, c;
        sincosf((float)((double)t * ROPE_INVF[j]), &s, &c);
        g_rope[idx] = make_float2(c, s);
        return;
    }
    else return;
    dst[0] = __floats2half2_rn(v.x, v.y);
    dst[1] = __floats2half2_rn(v.z, v.w);
}

// ======================= hgemm mainloop (256 threads, warp tile 32x64) =======================
#define GST 72
#define G_AB_HALVES 9216                 // 128*72
#define HGEMM_SMEM (4*G_AB_HALVES*2)     // 73728 B

#define HGEMM_MAINLOOP(A_, W_, K_)                                                        \
    const int tid  = threadIdx.x;                                                         \
    const int w    = tid >> 5;                                                            \
    const int lane = tid & 31;                                                            \
    const int g    = lane >> 2;                                                           \
    const int tig  = lane & 3;                                                            \
    const int wm   = w >> 1;                                                              \
    const int wn   = w & 1;                                                               \
    const int m0   = blockIdx.y * 128;                                                    \
    const int n0   = blockIdx.x * 128;                                                    \
    const uint32_t sb = smem_u32(hs);                                                     \
    const int mi = lane >> 3, ri = lane & 7;                                              \
    const int a_row = (mi & 1) * 8 + ri;                                                  \
    const int a_kof = (mi >> 1) * 8;                                                      \
    const int b_row = (mi >> 1) * 8 + ri;                                                 \
    const int b_kof = (mi & 1) * 8;                                                       \
    const uint32_t a_lane_off = (uint32_t)(((wm * 32 + a_row) * GST + a_kof) * 2);        \
    const uint32_t b_lane_off = (uint32_t)(((wn * 64 + b_row) * GST + b_kof) * 2);        \
    auto cp_tileAB = [&](int kt, int buf) {                                               \
        uint32_t adst = sb + (buf * G_AB_HALVES) * 2;                                     \
        uint32_t bdst = sb + ((2 * G_AB_HALVES) + buf * G_AB_HALVES) * 2;                 \
        const __half* as = (A_) + (size_t)m0 * (K_) + kt;                                 \
        const __half* ws = (W_) + (size_t)n0 * (K_) + kt;                                 \
        _Pragma("unroll")                                                                 \
        for (int j = 0; j < 4; j++) {                                                     \
            int lin = tid + 256 * j;                                                      \
            int row = lin >> 3, c = lin & 7;                                              \
            cp16(adst + (row * GST + c * 8) * 2, as + (size_t)row * (K_) + c * 8);        \
            cp16(bdst + (row * GST + c * 8) * 2, ws + (size_t)row * (K_) + c * 8);        \
        }                                                                                 \
    };                                                                                    \
    cp_tileAB(0, 0);                                                                      \
    CP_COMMIT(); CP_WAIT0();                                                              \
    __syncthreads();                                                                      \
    float acc[2][8][4];                                                                   \
    _Pragma("unroll")                                                                     \
    for (int f = 0; f < 2; f++)                                                           \
        _Pragma("unroll")                                                                 \
        for (int nt = 0; nt < 8; nt++)                                                    \
            _Pragma("unroll")                                                             \
            for (int i = 0; i < 4; i++) acc[f][nt][i] = 0.f;                              \
    const int nsteps = (K_) / 64;                                                         \
    for (int s = 0; s < nsteps; s++) {                                                    \
        const int cur = s & 1;                                                            \
        if (s + 1 < nsteps) { cp_tileAB((s + 1) * 64, cur ^ 1); CP_COMMIT(); }            \
        const uint32_t a_s = sb + (cur * G_AB_HALVES) * 2 + a_lane_off;                   \
        const uint32_t b_s = sb + ((2 * G_AB_HALVES) + cur * G_AB_HALVES) * 2 + b_lane_off;\
        _Pragma("unroll")                                                                 \
        for (int kk = 0; kk < 4; kk++) {                                                  \
            uint32_t afr[2][4];                                                           \
            _Pragma("unroll")                                                             \
            for (int f = 0; f < 2; f++)                                                   \
                LDSM_X4(afr[f][0], afr[f][1], afr[f][2], afr[f][3],                       \
                        a_s + (f * 16 * GST + kk * 16) * 2);                              \
            _Pragma("unroll")                                                             \
            for (int ntp = 0; ntp < 4; ntp++) {                                           \
                uint32_t b0a, b1a, b0b, b1b;                                              \
                LDSM_X4(b0a, b1a, b0b, b1b, b_s + (ntp * 16 * GST + kk * 16) * 2);        \
                mma_f16(acc[0][2*ntp],   afr[0], b0a, b1a);                               \
                mma_f16(acc[1][2*ntp],   afr[1], b0a, b1a);                               \
                mma_f16(acc[0][2*ntp+1], afr[0], b0b, b1b);                               \
                mma_f16(acc[1][2*ntp+1], afr[1], b0b, b1b);                               \
            }                                                                             \
        }                                                                                 \
        CP_WAIT0();                                                                       \
        __syncthreads();                                                                  \
    }

// ---------------- GEMM 1: in-projection, FUSED bias + table-RoPE + QKV split ----------------
__global__ __launch_bounds__(256, 2) void hgemm_rope(
    const __half* __restrict__ A, const __half* __restrict__ W,
    const float* __restrict__ bias)
{
    extern __shared__ __half hs[];
    HGEMM_MAINLOOP(A, W, EDIM)

    const int region = n0 / EDIM;          // 0=q, 1=k, 2=v (uniform per CTA)
    const float qsc = 0.125f * L2E;

    #pragma unroll
    for (int f = 0; f < 2; f++) {
        int r0 = m0 + wm * 32 + f * 16 + g;        // global row (t*BSZ + b)
        int ta = r0 >> 2, ba = r0 & 3;
        int tb = (r0 + 8) >> 2;
        #pragma unroll
        for (int nt = 0; nt < 8; nt++) {
            int gcol = n0 + wn * 64 + nt * 8 + 2 * tig;
            float bx = bias[gcol], by = bias[gcol + 1];
            float x0 = acc[f][nt][0] + bx, x1 = acc[f][nt][1] + by;
            float x2 = acc[f][nt][2] + bx, x3 = acc[f][nt][3] + by;
            int c = gcol - region * EDIM;
            int h = c >> 6, d = c & 63, j = d >> 1;
            size_t oa = ((size_t)(ba * NH + h) * TLEN + ta) * HD + d;
            size_t ob = ((size_t)(ba * NH + h) * TLEN + tb) * HD + d;
            if (region == 2) {
                *(__half2*)(g_vh + oa) = __floats2half2_rn(x0, x1);
                *(__half2*)(g_vh + ob) = __floats2half2_rn(x2, x3);
            } else {
                float2 csa = g_rope[ta * 32 + j];
                float2 csb = g_rope[tb * 32 + j];
                float y0 = x0 * csa.x - x1 * csa.y, y1 = x1 * csa.x + x0 * csa.y;
                float y2 = x2 * csb.x - x3 * csb.y, y3 = x3 * csb.x + x2 * csb.y;
                if (region == 0) {
                    *(__half2*)(g_qh + oa) = __floats2half2_rn(y0 * qsc, y1 * qsc);
                    *(__half2*)(g_qh + ob) = __floats2half2_rn(y2 * qsc, y3 * qsc);
                } else {
                    *(__half2*)(g_kh + oa) = __floats2half2_rn(y0, y1);
                    *(__half2*)(g_kh + ob) = __floats2half2_rn(y2, y3);
                }
            }
        }
    }
}

// ---------------- GEMM 2: out-projection, plain bias epilogue ----------------
__global__ __launch_bounds__(256, 2) void hgemm_bias(
    const __half* __restrict__ A, const __half* __restrict__ W,
    const float* __restrict__ bias, float* __restrict__ C,
    int N, int K)
{
    extern __shared__ __half hs[];
    HGEMM_MAINLOOP(A, W, K)

    #pragma unroll
    for (int f = 0; f < 2; f++) {
        int r0 = m0 + wm * 32 + f * 16 + g;
        #pragma unroll
        for (int nt = 0; nt < 8; nt++) {
            int c = n0 + wn * 64 + nt * 8 + 2 * tig;
            float bx = bias[c], by = bias[c + 1];
            *(float2*)(C + (size_t)r0 * N + c)       = make_float2(acc[f][nt][0] + bx, acc[f][nt][1] + by);
            *(float2*)(C + (size_t)(r0 + 8) * N + c) = make_float2(acc[f][nt][2] + bx, acc[f][nt][3] + by);
        }
    }
}

// ---------------- fp16 mma flash attention: 128-key tiles, Q-smem reuse ----------------
// buffers (halves): K[0]=0, V[0]=9216, K[1]=18432, V[1]=27648; Q staged at 18432 (=K[1])
#define FT_HALVES 9216          // 128 rows * 72
#define FK_OFF(b) ((b) ? 18432 : 0)
#define FV_OFF(b) ((b) ? 27648 : 9216)
#define FQ_OFF    18432
#define FLASH_SMEM (36864*2)    // 73728 B

__global__ __launch_bounds__(128, 3) void flash_h_kernel()
{
    extern __shared__ __half hs[];
    const int tid  = threadIdx.x;
    const int w    = tid >> 5;
    const int lane = tid & 31;
    const int g    = lane >> 2;
    const int tig  = lane & 3;
    const int bh   = blockIdx.y;
    const int qt   = blockIdx.x;
    const uint32_t sb = smem_u32(hs);

    const bool mnz = (g_mask_nz != 0);

    const int qbase = qt * 128 + w * 32 + g;

    const __half* qg = g_qh + (size_t)bh * TLEN * HD;
    const __half* kg = g_kh + (size_t)bh * TLEN * HD;
    const __half* vg = g_vh + (size_t)bh * TLEN * HD;

    const int mi = lane >> 3, ri = lane & 7;
    const int b_row = (mi >> 1) * 8 + ri;
    const int b_kof = (mi & 1) * 8;
    const uint32_t b_lane_off = (uint32_t)((b_row * GST + b_kof) * 2);
    const int v_row = (mi & 1) * 8 + ri;
    const int v_kof = (mi >> 1) * 8;
    const uint32_t v_lane_off = (uint32_t)((v_row * GST + v_kof) * 2);

    // ---- prolog: Q tile (into K[1] region) + K/V tile 0 (128 keys)
    #pragma unroll
    for (int j = 0; j < 8; j++) {
        int lin = tid + 128 * j;
        int row = lin >> 3, c = lin & 7;
        cp16(sb + (FQ_OFF + row * GST + c * 8) * 2, qg + (size_t)(qt * 128 + row) * HD + c * 8);
        cp16(sb + (FK_OFF(0) + row * GST + c * 8) * 2, kg + (size_t)row * HD + c * 8);
        cp16(sb + (FV_OFF(0) + row * GST + c * 8) * 2, vg + (size_t)row * HD + c * 8);
    }
    CP_COMMIT(); CP_WAIT0();
    __syncthreads();

    // ---- Q A-frags (resident): 2 m16 frags per warp
    uint32_t qa[2][4][4];
    {
        const uint32_t* q32 = (const uint32_t*)(hs + FQ_OFF);
        #pragma unroll
        for (int f = 0; f < 2; f++) {
            int r0 = w * 32 + f * 16 + g, r1 = r0 + 8;
            #pragma unroll
            for (int ks = 0; ks < 4; ks++) {
                const uint32_t* p0 = q32 + r0 * 36 + ks * 8 + tig;
                const uint32_t* p1 = q32 + r1 * 36 + ks * 8 + tig;
                qa[f][ks][0] = p0[0]; qa[f][ks][1] = p1[0];
                qa[f][ks][2] = p0[4]; qa[f][ks][3] = p1[4];
            }
        }
    }
    __syncthreads();   // all warps done reading Q before iter0 prefetch overwrites it

    float oacc[2][8][4];
    #pragma unroll
    for (int f = 0; f < 2; f++)
        #pragma unroll
        for (int nt = 0; nt < 8; nt++)
            #pragma unroll
            for (int i = 0; i < 4; i++) oacc[f][nt][i] = 0.f;
    float lsum[4] = {0.f, 0.f, 0.f, 0.f};

    const uint32_t* mrb = (const uint32_t*)(g_maskh + (size_t)qbase * TLEN);
    const int RW = TLEN / 2;

    for (int it = 0; it < 16; it++) {
        const int cur = it & 1;

        // prefetch next 128-key K/V tile
        if (it < 15) {
            const __half* ksrc = kg + (size_t)(it + 1) * 128 * HD;
            const __half* vsrc = vg + (size_t)(it + 1) * 128 * HD;
            uint32_t kdst = sb + FK_OFF(cur ^ 1) * 2;
            uint32_t vdst = sb + FV_OFF(cur ^ 1) * 2;
            #pragma unroll
            for (int j = 0; j < 8; j++) {
                int lin = tid + 128 * j;
                int row = lin >> 3, c = lin & 7;
                cp16(kdst + (row * GST + c * 8) * 2, ksrc + (size_t)row * HD + c * 8);
                cp16(vdst + (row * GST + c * 8) * 2, vsrc + (size_t)row * HD + c * 8);
            }
            CP_COMMIT();
        }

        const uint32_t kb = sb + FK_OFF(cur) * 2 + b_lane_off;
        const uint32_t vb = sb + FV_OFF(cur) * 2 + v_lane_off;
        const int mo = it * 64;     // half2 offset of this 128-key tile

        uint32_t lacc[4] = {0u, 0u, 0u, 0u};

        // ---- 8 slices of 16 keys
        #pragma unroll
        for (int np = 0; np < 8; np++) {
            float s[2][2][4];
            #pragma unroll
            for (int f = 0; f < 2; f++)
                #pragma unroll
                for (int n = 0; n < 2; n++)
                    #pragma unroll
                    for (int i = 0; i < 4; i++) s[f][n][i] = 0.f;
            #pragma unroll
            for (int ks = 0; ks < 4; ks++) {
                uint32_t b0a, b1a, b0b, b1b;
                LDSM_X4(b0a, b1a, b0b, b1b, kb + (np * 16 * GST + ks * 16) * 2);
                mma_f16(s[0][0], qa[0][ks], b0a, b1a);
                mma_f16(s[0][1], qa[0][ks], b0b, b1b);
                mma_f16(s[1][0], qa[1][ks], b0a, b1a);
                mma_f16(s[1][1], qa[1][ks], b0b, b1b);
            }

            uint32_t pa[2][4];
            #pragma unroll
            for (int f = 0; f < 2; f++) {
                uint32_t x0 = cvt_h2(s[f][0][0], s[f][0][1]);
                uint32_t x1 = cvt_h2(s[f][0][2], s[f][0][3]);
                uint32_t x2 = cvt_h2(s[f][1][0], s[f][1][1]);
                uint32_t x3 = cvt_h2(s[f][1][2], s[f][1][3]);
                if (mnz) {
                    const uint32_t* m0p = mrb + (size_t)(f * 16) * RW + mo;
                    const uint32_t* m1p = mrb + (size_t)(f * 16 + 8) * RW + mo;
                    x0 = hadd2u(x0, __ldg(m0p + (2*np) * 4 + tig));
                    x1 = hadd2u(x1, __ldg(m1p + (2*np) * 4 + tig));
                    x2 = hadd2u(x2, __ldg(m0p + (2*np+1) * 4 + tig));
                    x3 = hadd2u(x3, __ldg(m1p + (2*np+1) * 4 + tig));
                }
                pa[f][0] = ex2_h2(x0);
                pa[f][1] = ex2_h2(x1);
                pa[f][2] = ex2_h2(x2);
                pa[f][3] = ex2_h2(x3);
                lacc[2*f]   = hadd2u(lacc[2*f],   hadd2u(pa[f][0], pa[f][2]));
                lacc[2*f+1] = hadd2u(lacc[2*f+1], hadd2u(pa[f][1], pa[f][3]));
            }

            #pragma unroll
            for (int ntp = 0; ntp < 4; ntp++) {
                uint32_t b0a, b1a, b0b, b1b;
                LDSM_X4T(b0a, b1a, b0b, b1b, vb + (np * 16 * GST + ntp * 16) * 2);
                mma_f16(oacc[0][2*ntp],   pa[0], b0a, b1a);
                mma_f16(oacc[0][2*ntp+1], pa[0], b0b, b1b);
                mma_f16(oacc[1][2*ntp],   pa[1], b0a, b1a);
                mma_f16(oacc[1][2*ntp+1], pa[1], b0b, b1b);
            }
        }

        // flush fp16x2 tile sums into fp32
        #pragma unroll
        for (int r = 0; r < 4; r++) {
            float2 f2 = __half22float2(*(__half2*)&lacc[r]);
            lsum[r] += f2.x + f2.y;
        }

        CP_WAIT0();
        __syncthreads();
    }

    #pragma unroll
    for (int r = 0; r < 4; r++) {
        lsum[r] += __shfl_xor_sync(0xffffffffu, lsum[r], 1);
        lsum[r] += __shfl_xor_sync(0xffffffffu, lsum[r], 2);
    }
    int b = bh / NH, h = bh % NH;
    #pragma unroll
    for (int f = 0; f < 2; f++) {
        float inv0 = 1.f / lsum[2*f];
        float inv1 = 1.f / lsum[2*f+1];
        int r0 = qbase + f * 16;
        __half* o0 = g_attnh + ((size_t)r0 * BSZ + b) * EDIM + h * HD;
        __half* o1 = g_attnh + ((size_t)(r0 + 8) * BSZ + b) * EDIM + h * HD;
        #pragma unroll
        for (int nt = 0; nt < 8; nt++) {
            int c = nt * 8 + 2 * tig;
            *(__half2*)(o0 + c) = __floats2half2_rn(oacc[f][nt][0] * inv0, oacc[f][nt][1] * inv0);
            *(__half2*)(o1 + c) = __floats2half2_rn(oacc[f][nt][2] * inv1, oacc[f][nt][3] * inv1);
        }
    }
}

// ---------------- launch ----------------
extern "C" void kernel_launch(void* const* d_in, const int* in_sizes, int n_in,
                              void* d_out, int out_size)
{
    const float* query = (const float*)d_in[0];
    const float* mask  = (const float*)d_in[1];
    const float* win   = (const float*)d_in[2];
    const float* bin   = (const float*)d_in[3];
    const float* wout  = (const float*)d_in[4];
    const float* bout  = (const float*)d_in[5];
    float* out = (float*)d_out;

    void* p;
    cudaGetSymbolAddress(&p, g_qin);    __half* qin = (__half*)p;
    cudaGetSymbolAddress(&p, g_winh);   __half* winh = (__half*)p;
    cudaGetSymbolAddress(&p, g_wouth);  __half* wouth = (__half*)p;
    cudaGetSymbolAddress(&p, g_attnh);  __half* attnh = (__half*)p;

    static bool attr_set = false;
    if (!attr_set) {
        cudaFuncSetAttribute(hgemm_rope,
                             cudaFuncAttributeMaxDynamicSharedMemorySize, HGEMM_SMEM);
        cudaFuncSetAttribute(hgemm_bias,
                             cudaFuncAttributeMaxDynamicSharedMemorySize, HGEMM_SMEM);
        cudaFuncSetAttribute(flash_h_kernel,
                             cudaFuncAttributeMaxDynamicSharedMemorySize, FLASH_SMEM);
        attr_set = true;
    }

    // 0) convert inputs to fp16 + build rope table (single kernel)
    int cvt_total = CVT_N1 + CVT_N2 + CVT_N3 + CVT_N4 + CVT_N5;
    cvt_kernel<<<(cvt_total + 255) / 256, 256>>>((const float4*)query,
                                                 (const float4*)win,
                                                 (const float4*)wout,
                                                 (const float4*)mask);

    // 1) in-projection with fused bias + table-RoPE + QKV split
    dim3 g1(E3 / 128, (TLEN * BSZ) / 128);
    hgemm_rope<<<g1, 256, HGEMM_SMEM>>>(qin, winh, bin);

    // 2) flash attention (128-key tiles)
    dim3 gf(TLEN / 128, BSZ * NH);
    flash_h_kernel<<<gf, 128, FLASH_SMEM>>>();

    // 3) out-projection
    dim3 g2(EDIM / 128, (TLEN * BSZ) / 128);
    hgemm_bias<<<g2, 256, HGEMM_SMEM>>>(attnh, wouth, bout, out, EDIM, EDIM);
}